// round 10
// baseline (speedup 1.0000x reference)
#include <cuda_runtime.h>

// Problem: inputs [8,128,128,64] f32, beta [64,16] f32
// out[e, c] = inputs[e] * u[e%64, c],  u = beta^2 / rowsum(beta^2)
// out flat: n4 = 2^25 float4s. (i = (g>>2)&63, j = g&3) has period 256 in g;
// grid stride is a multiple of 256 -> per-thread u is loop-invariant.
//
// R10 = R3's exact winning body (batch-8 loads, dense strided sweep,
// 1024 blocks) + __launch_bounds__(256,8) to cap regs at 32 and lift
// residency from 6 to ~7-8 blocks/SM (occ ~84%, single full wave).

#define D_DIM 64
#define BLOCKS 1024
#define THREADS 256
#define STRIDE (BLOCKS * THREADS)      // 2^18 float4s per grid step
#define ITERS 128                      // 2^25 / STRIDE
#define BATCH 8
#define PASSES (ITERS / BATCH)         // 16

__global__ void __launch_bounds__(THREADS, 8) fused_broadcast_mul(
    const float* __restrict__ in, const float* __restrict__ beta,
    float4* __restrict__ out) {
    unsigned int g = blockIdx.x * THREADS + threadIdx.x;
    const unsigned int i = (g >> 2) & (D_DIM - 1);  // beta row
    const unsigned int j = g & 3u;                  // float4 quarter of the row

    // ---- one-time prologue: this thread's u quarter, in registers ----
    const float4* br = reinterpret_cast<const float4*>(beta) + i * 4;
    float4 q0 = __ldg(br + 0);
    float4 q1 = __ldg(br + 1);
    float4 q2 = __ldg(br + 2);
    float4 q3 = __ldg(br + 3);
    float s = q0.x * q0.x + q0.y * q0.y + q0.z * q0.z + q0.w * q0.w
            + q1.x * q1.x + q1.y * q1.y + q1.z * q1.z + q1.w * q1.w
            + q2.x * q2.x + q2.y * q2.y + q2.z * q2.z + q2.w * q2.w
            + q3.x * q3.x + q3.y * q3.y + q3.z * q3.z + q3.w * q3.w;
    float inv = 1.0f / s;
    float4 bq = (j == 0) ? q0 : (j == 1) ? q1 : (j == 2) ? q2 : q3;
    const float4 u = make_float4(bq.x * bq.x * inv, bq.y * bq.y * inv,
                                 bq.z * bq.z * inv, bq.w * bq.w * inv);

    // ---- 16 passes: 8 independent loads, then 8 FMUL+STG.128 ----
    const float* ip = in + (g >> 2);
    float4* op = out + g;

    for (int p = 0; p < PASSES; ++p) {
        float x[BATCH];
#pragma unroll
        for (int k = 0; k < BATCH; ++k)
            x[k] = __ldg(ip + k * (STRIDE / 4));   // input fits L2 -> mostly hits
#pragma unroll
        for (int k = 0; k < BATCH; ++k) {
            float4 r = make_float4(x[k] * u.x, x[k] * u.y,
                                   x[k] * u.z, x[k] * u.w);
            __stcs(op + k * STRIDE, r);            // evict-first write stream
        }
        ip += (STRIDE / 4) * BATCH;
        op += STRIDE * BATCH;
    }
}

extern "C" void kernel_launch(void* const* d_in, const int* in_sizes, int n_in,
                              void* d_out, int out_size) {
    const float* inputs = (const float*)d_in[0];  // 8*128*128*64 = 8388608
    const float* beta   = (const float*)d_in[1];  // 64*16 = 1024
    float4* out = (float4*)d_out;

    fused_broadcast_mul<<<BLOCKS, THREADS>>>(inputs, beta, out);
}